// round 2
// baseline (speedup 1.0000x reference)
#include <cuda_runtime.h>

#define IN_CH 50
#define OUT_CH 121
#define YPITCH 128
#define MAX_N 100000

// Node-level Y = X @ W1, padded to 128 cols (pad cols are exactly 0).
__device__ __align__(16) float g_y[MAX_N * YPITCH];

// ---- packed fp32x2 helpers (FFMA2: 2 FMA lanes per instruction on sm_103a) ----
__device__ __forceinline__ void fma2(unsigned long long &d, unsigned long long a, unsigned long long b) {
    asm("fma.rn.f32x2 %0, %1, %2, %0;" : "+l"(d) : "l"(a), "l"(b));
}
__device__ __forceinline__ unsigned long long pack2(float x, float y) {
    unsigned long long r;
    asm("mov.b64 %0, {%1, %2};" : "=l"(r) : "f"(x), "f"(y));
    return r;
}
__device__ __forceinline__ float2 unpack2(unsigned long long v) {
    float2 r;
    asm("mov.b64 {%0, %1}, %2;" : "=f"(r.x), "=f"(r.y) : "l"(v));
    return r;
}

// ============================================================================
// Kernel A: Y[N,128] = X[N,50] @ W1[50,121]  (cols 121..127 = 0 via zero-padded W1s)
// BM=128 nodes, BN=128, K=50. 256 threads, 8x8 microtile per thread.
// ============================================================================
__global__ void __launch_bounds__(256, 1) node_gemm(const float* __restrict__ x,
                                                    const float* __restrict__ W1,
                                                    int N) {
    extern __shared__ float sm[];
    float* Xs  = sm;                 // [k][m], stride 132 (bank-stagger)
    float* W1s = Xs + IN_CH * 132;   // [k][n], stride 128, zero-padded n>=121

    int tid = threadIdx.x;
    int e0 = blockIdx.x * 128;

    // Load X tile, transpose into Xs[k][m]
    for (int i = tid; i < 128 * IN_CH; i += 256) {
        int m = i / IN_CH, k = i - m * IN_CH;
        int node = e0 + m;
        Xs[k * 132 + m] = (node < N) ? x[(long)node * IN_CH + k] : 0.f;
    }
    // Load W1 zero-padded to 128 cols
    for (int i = tid; i < IN_CH * 128; i += 256) {
        int k = i >> 7, n = i & 127;
        W1s[i] = (n < OUT_CH) ? W1[k * OUT_CH + n] : 0.f;
    }
    __syncthreads();

    int tx = tid & 15, ty = tid >> 4;
    unsigned long long acc[8][4];
#pragma unroll
    for (int i = 0; i < 8; i++)
#pragma unroll
        for (int j = 0; j < 4; j++) acc[i][j] = 0ULL;

    const float* ap  = Xs + ty * 8;
    const float* bp0 = W1s + tx * 4;        // n split: [tx*4, tx*4+3] and [64+tx*4, ...]
    const float* bp1 = W1s + 64 + tx * 4;   // (avoids LDS.128 bank conflicts of 8-wide)

#pragma unroll 5
    for (int k = 0; k < IN_CH; k++) {
        float4 a0 = *(const float4*)(ap + k * 132);
        float4 a1 = *(const float4*)(ap + k * 132 + 4);
        float4 b0 = *(const float4*)(bp0 + k * 128);
        float4 b1 = *(const float4*)(bp1 + k * 128);
        unsigned long long bb0 = pack2(b0.x, b0.y);
        unsigned long long bb1 = pack2(b0.z, b0.w);
        unsigned long long bb2 = pack2(b1.x, b1.y);
        unsigned long long bb3 = pack2(b1.z, b1.w);
        float am[8] = {a0.x, a0.y, a0.z, a0.w, a1.x, a1.y, a1.z, a1.w};
#pragma unroll
        for (int i = 0; i < 8; i++) {
            unsigned long long aa = pack2(am[i], am[i]);
            fma2(acc[i][0], aa, bb0);
            fma2(acc[i][1], aa, bb1);
            fma2(acc[i][2], aa, bb2);
            fma2(acc[i][3], aa, bb3);
        }
    }

#pragma unroll
    for (int i = 0; i < 8; i++) {
        int node = e0 + ty * 8 + i;
        if (node < N) {
            float2 v0 = unpack2(acc[i][0]);
            float2 v1 = unpack2(acc[i][1]);
            float2 v2 = unpack2(acc[i][2]);
            float2 v3 = unpack2(acc[i][3]);
            float4 lo = make_float4(v0.x, v0.y, v1.x, v1.y);
            float4 hi = make_float4(v2.x, v2.y, v3.x, v3.y);
            *(float4*)(g_y + (long)node * YPITCH + tx * 4) = lo;
            *(float4*)(g_y + (long)node * YPITCH + 64 + tx * 4) = hi;
        }
    }
}

// ============================================================================
// Kernel B: per 128-edge tile:
//   H[m][k] = relu((1+eps)*Y[row[m]][k] + Y[col[m]][k] + b1[k])   (stored [k][m])
//   OUT[m][n] = sum_k H[m][k] * W2[k][n] + b2[n]
// edge_index arrives as INT32 (harness converts int64 -> int32).
// ============================================================================
__global__ void __launch_bounds__(256, 1) edge_gemm(const int* __restrict__ ei,
                                                    const float* __restrict__ b1,
                                                    const float* __restrict__ W2,
                                                    const float* __restrict__ b2,
                                                    const float* __restrict__ epsp,
                                                    float* __restrict__ out,
                                                    int E, int N) {
    extern __shared__ float sm[];
    float* Hs  = sm;                 // [k 0..123][m 0..127] = 15872 floats (reused as C stage)
    float* Ws  = Hs + 124 * 128;     // [k 0..120][n 0..127] = 15488 floats, zero-padded n>=121
    float* b1s = Ws + 121 * 128;     // 128 (zero-padded)
    float* b2s = b1s + 128;          // 128 (zero-padded)
    int* rows_s = (int*)(b2s + 128); // 128
    int* cols_s = rows_s + 128;      // 128

    int tid = threadIdx.x;
    int e0 = blockIdx.x * 128;
    int rem = E - e0; if (rem > 128) rem = 128;

    if (tid < 128) {
        int r = 0, c = 0;
        if (tid < rem) {
            r = ei[e0 + tid];
            c = ei[E + e0 + tid];
        }
        // defensive clamp: wrong dtype assumption degrades to rel_err, not a crash
        if (r < 0) r = 0; if (r >= N) r = N - 1;
        if (c < 0) c = 0; if (c >= N) c = N - 1;
        rows_s[tid] = r;
        cols_s[tid] = c;
        b1s[tid] = (tid < OUT_CH) ? b1[tid] : 0.f;
        b2s[tid] = (tid < OUT_CH) ? b2[tid] : 0.f;
    }
    // W2 -> smem, zero-padded cols
    for (int i = tid; i < 121 * 128; i += 256) {
        int k = i >> 7, n = i & 127;
        Ws[i] = (n < OUT_CH) ? W2[k * OUT_CH + n] : 0.f;
    }
    __syncthreads();

    // Build H (gather from L2-resident g_y), store transposed [k][m]
    float coef = 1.f + epsp[0];
    for (int i = tid; i < 128 * 31; i += 256) {   // 31 float4 chunks cover k 0..123
        int m = i & 127;
        int cb = (i >> 7) << 2;                   // 0,4,...,120
        long r = rows_s[m];
        long c = cols_s[m];
        float4 yr = *(const float4*)(g_y + r * YPITCH + cb);
        float4 yc = *(const float4*)(g_y + c * YPITCH + cb);
        Hs[(cb + 0) * 128 + m] = fmaxf(fmaf(coef, yr.x, yc.x) + b1s[cb + 0], 0.f);
        Hs[(cb + 1) * 128 + m] = fmaxf(fmaf(coef, yr.y, yc.y) + b1s[cb + 1], 0.f);
        Hs[(cb + 2) * 128 + m] = fmaxf(fmaf(coef, yr.z, yc.z) + b1s[cb + 2], 0.f);
        Hs[(cb + 3) * 128 + m] = fmaxf(fmaf(coef, yr.w, yc.w) + b1s[cb + 3], 0.f);
    }
    __syncthreads();

    int tx = tid & 15, ty = tid >> 4;
    unsigned long long acc[8][4];
#pragma unroll
    for (int i = 0; i < 8; i++)
#pragma unroll
        for (int j = 0; j < 4; j++) acc[i][j] = 0ULL;

    const float* ap  = Hs + ty * 8;
    const float* bp0 = Ws + tx * 4;
    const float* bp1 = Ws + 64 + tx * 4;

#pragma unroll 4
    for (int k = 0; k < OUT_CH; k++) {
        float4 a0 = *(const float4*)(ap + k * 128);
        float4 a1 = *(const float4*)(ap + k * 128 + 4);
        float4 b0 = *(const float4*)(bp0 + k * 128);
        float4 b1v = *(const float4*)(bp1 + k * 128);
        unsigned long long bb0 = pack2(b0.x, b0.y);
        unsigned long long bb1 = pack2(b0.z, b0.w);
        unsigned long long bb2 = pack2(b1v.x, b1v.y);
        unsigned long long bb3 = pack2(b1v.z, b1v.w);
        float am[8] = {a0.x, a0.y, a0.z, a0.w, a1.x, a1.y, a1.z, a1.w};
#pragma unroll
        for (int i = 0; i < 8; i++) {
            unsigned long long aa = pack2(am[i], am[i]);
            fma2(acc[i][0], aa, bb0);
            fma2(acc[i][1], aa, bb1);
            fma2(acc[i][2], aa, bb2);
            fma2(acc[i][3], aa, bb3);
        }
    }
    __syncthreads();   // everyone done reading Hs; reuse as C stage [m][121]

    float* Cs = Hs;
    int n0 = tx * 4, n1 = 64 + tx * 4;
#pragma unroll
    for (int i = 0; i < 8; i++) {
        int m = ty * 8 + i;
        float2 v0 = unpack2(acc[i][0]);
        float2 v1 = unpack2(acc[i][1]);
        float2 v2 = unpack2(acc[i][2]);
        float2 v3 = unpack2(acc[i][3]);
        float* cr = Cs + m * OUT_CH;
        cr[n0 + 0] = v0.x + b2s[n0 + 0];
        cr[n0 + 1] = v0.y + b2s[n0 + 1];
        cr[n0 + 2] = v1.x + b2s[n0 + 2];
        cr[n0 + 3] = v1.y + b2s[n0 + 3];
        if (n1 + 0 < OUT_CH) cr[n1 + 0] = v2.x + b2s[n1 + 0];
        if (n1 + 1 < OUT_CH) cr[n1 + 1] = v2.y + b2s[n1 + 1];
        if (n1 + 2 < OUT_CH) cr[n1 + 2] = v3.x + b2s[n1 + 2];
        if (n1 + 3 < OUT_CH) cr[n1 + 3] = v3.y + b2s[n1 + 3];
    }
    __syncthreads();

    // Coalesced write-out of the tile
    for (int i = tid; i < rem * OUT_CH; i += 256) {
        int m = i / OUT_CH;
        int c = i - m * OUT_CH;
        out[(long)(e0 + m) * OUT_CH + c] = Cs[m * OUT_CH + c];
    }
}

extern "C" void kernel_launch(void* const* d_in, const int* in_sizes, int n_in,
                              void* d_out, int out_size) {
    const float* x   = (const float*)d_in[0];
    const int*   ei  = (const int*)d_in[1];      // edge_index delivered as int32
    const float* W1  = (const float*)d_in[2];
    const float* b1  = (const float*)d_in[3];
    const float* W2  = (const float*)d_in[4];
    const float* b2  = (const float*)d_in[5];
    const float* eps = (const float*)d_in[6];
    float* out = (float*)d_out;

    int N = in_sizes[0] / IN_CH;
    int E = in_sizes[1] / 2;

    size_t smA = (size_t)(IN_CH * 132 + IN_CH * 128) * sizeof(float);           // 52,000 B
    size_t smB = (size_t)(124 * 128 + 121 * 128 + 128 + 128) * sizeof(float)
               + 256 * sizeof(int);                                             // 127,488 B
    cudaFuncSetAttribute(node_gemm, cudaFuncAttributeMaxDynamicSharedMemorySize, (int)smA);
    cudaFuncSetAttribute(edge_gemm, cudaFuncAttributeMaxDynamicSharedMemorySize, (int)smB);

    node_gemm<<<(N + 127) / 128, 256, smA>>>(x, W1, N);
    edge_gemm<<<(E + 127) / 128, 256, smB>>>(ei, b1, W2, b2, eps, out, E, N);
}

// round 4
// speedup vs baseline: 1.3457x; 1.3457x over previous
#include <cuda_runtime.h>
#include <cuda_bf16.h>
#include <cstdint>

#define IN_CH 50
#define OUT_CH 121
#define YPITCH 128
#define MAX_N 100000

__device__ __align__(16) float g_y[MAX_N * YPITCH];

// ---------------------------------------------------------------------------
// helpers
// ---------------------------------------------------------------------------
__device__ __forceinline__ uint32_t smem_u32(const void* p) {
    uint32_t a;
    asm("{ .reg .u64 t; cvta.to.shared.u64 t, %1; cvt.u32.u64 %0, t; }" : "=r"(a) : "l"(p));
    return a;
}

#define LDSM_X4(r0, r1, r2, r3, a) \
    asm volatile("ldmatrix.sync.aligned.m8n8.x4.shared.b16 {%0,%1,%2,%3}, [%4];" \
                 : "=r"(r0), "=r"(r1), "=r"(r2), "=r"(r3) : "r"(a))

__device__ __forceinline__ void mma16816(float* c, const uint32_t* a, uint32_t b0, uint32_t b1) {
    asm volatile(
        "mma.sync.aligned.m16n8k16.row.col.f32.bf16.bf16.f32 "
        "{%0,%1,%2,%3}, {%4,%5,%6,%7}, {%8,%9}, {%0,%1,%2,%3};"
        : "+f"(c[0]), "+f"(c[1]), "+f"(c[2]), "+f"(c[3])
        : "r"(a[0]), "r"(a[1]), "r"(a[2]), "r"(a[3]), "r"(b0), "r"(b1));
}

// FFMA2 helpers (node kernel)
__device__ __forceinline__ void fma2(unsigned long long &d, unsigned long long a, unsigned long long b) {
    asm("fma.rn.f32x2 %0, %1, %2, %0;" : "+l"(d) : "l"(a), "l"(b));
}
__device__ __forceinline__ unsigned long long pack2(float x, float y) {
    unsigned long long r; asm("mov.b64 %0, {%1, %2};" : "=l"(r) : "f"(x), "f"(y)); return r;
}
__device__ __forceinline__ float2 unpack2(unsigned long long v) {
    float2 r; asm("mov.b64 {%0, %1}, %2;" : "=f"(r.x), "=f"(r.y) : "l"(v)); return r;
}

// ============================================================================
// Kernel A: Y[N,128] = X[N,50] @ W1[50,121], zero-padded cols (validated R2)
// ============================================================================
__global__ void __launch_bounds__(256, 1) node_gemm(const float* __restrict__ x,
                                                    const float* __restrict__ W1,
                                                    int N) {
    extern __shared__ float sm[];
    float* Xs  = sm;
    float* W1s = Xs + IN_CH * 132;

    int tid = threadIdx.x;
    int e0 = blockIdx.x * 128;

    for (int i = tid; i < 128 * IN_CH; i += 256) {
        int m = i / IN_CH, k = i - m * IN_CH;
        int node = e0 + m;
        Xs[k * 132 + m] = (node < N) ? x[(long)node * IN_CH + k] : 0.f;
    }
    for (int i = tid; i < IN_CH * 128; i += 256) {
        int k = i >> 7, n = i & 127;
        W1s[i] = (n < OUT_CH) ? W1[k * OUT_CH + n] : 0.f;
    }
    __syncthreads();

    int tx = tid & 15, ty = tid >> 4;
    unsigned long long acc[8][4];
#pragma unroll
    for (int i = 0; i < 8; i++)
#pragma unroll
        for (int j = 0; j < 4; j++) acc[i][j] = 0ULL;

    const float* ap  = Xs + ty * 8;
    const float* bp0 = W1s + tx * 4;
    const float* bp1 = W1s + 64 + tx * 4;

#pragma unroll 5
    for (int k = 0; k < IN_CH; k++) {
        float4 a0 = *(const float4*)(ap + k * 132);
        float4 a1 = *(const float4*)(ap + k * 132 + 4);
        float4 b0 = *(const float4*)(bp0 + k * 128);
        float4 b1 = *(const float4*)(bp1 + k * 128);
        unsigned long long bb0 = pack2(b0.x, b0.y);
        unsigned long long bb1 = pack2(b0.z, b0.w);
        unsigned long long bb2 = pack2(b1.x, b1.y);
        unsigned long long bb3 = pack2(b1.z, b1.w);
        float am[8] = {a0.x, a0.y, a0.z, a0.w, a1.x, a1.y, a1.z, a1.w};
#pragma unroll
        for (int i = 0; i < 8; i++) {
            unsigned long long aa = pack2(am[i], am[i]);
            fma2(acc[i][0], aa, bb0);
            fma2(acc[i][1], aa, bb1);
            fma2(acc[i][2], aa, bb2);
            fma2(acc[i][3], aa, bb3);
        }
    }

#pragma unroll
    for (int i = 0; i < 8; i++) {
        int node = e0 + ty * 8 + i;
        if (node < N) {
            float2 v0 = unpack2(acc[i][0]);
            float2 v1 = unpack2(acc[i][1]);
            float2 v2 = unpack2(acc[i][2]);
            float2 v3 = unpack2(acc[i][3]);
            *(float4*)(g_y + (long)node * YPITCH + tx * 4)      = make_float4(v0.x, v0.y, v1.x, v1.y);
            *(float4*)(g_y + (long)node * YPITCH + 64 + tx * 4) = make_float4(v2.x, v2.y, v3.x, v3.y);
        }
    }
}

// ============================================================================
// Kernel B: persistent bf16x3-split mma.sync edge GEMM
// smem layout (bytes from 1KB-aligned base), row pitch 272B everywhere:
//   W2hi [128n][272B]         @ 0       (34816)
//   W2lo                      @ 34816   (34816)
//   H: warp w, buf b, hi/lo:  @ 69632 + w*17408 + b*8704 + hilo*4352
//   b1s[128]                  @ 208896
//   b2s[128]                  @ 209408
// total 209920 (+1024 align slack)
// ============================================================================
#define PITCH 272
#define OFF_W2HI 0
#define OFF_W2LO 34816
#define OFF_H    69632
#define OFF_B1   208896
#define OFF_B2   209408
#define SMEM_EDGE (209920 + 1024)

__global__ void __launch_bounds__(256, 1) edge_mma(const int* __restrict__ ei,
                                                   const float* __restrict__ b1,
                                                   const float* __restrict__ W2,
                                                   const float* __restrict__ b2,
                                                   const float* __restrict__ epsp,
                                                   float* __restrict__ out,
                                                   int E, int N, int T) {
    extern __shared__ char smraw[];
    char* sm = (char*)(((uintptr_t)smraw + 1023) & ~(uintptr_t)1023);
    uint32_t sb = smem_u32(sm);

    float* b1s = (float*)(sm + OFF_B1);
    float* b2s = (float*)(sm + OFF_B2);

    int tid = threadIdx.x, wid = tid >> 5, lane = tid & 31;

    // ---- one-time: W2 split into bf16 hi/lo, [n][k] padded rows; biases ----
    if (tid < 128) {
        b1s[tid] = (tid < OUT_CH) ? b1[tid] : 0.f;
        b2s[tid] = (tid < OUT_CH) ? b2[tid] : 0.f;
    }
    for (int i = tid; i < 128 * 128; i += 256) {
        int n = i >> 7, k = i & 127;
        float v = (n < OUT_CH && k < OUT_CH) ? W2[k * OUT_CH + n] : 0.f;
        __nv_bfloat16 hv = __float2bfloat16(v);
        __nv_bfloat16 lv = __float2bfloat16(v - __bfloat162float(hv));
        *(__nv_bfloat16*)(sm + OFF_W2HI + n * PITCH + k * 2) = hv;
        *(__nv_bfloat16*)(sm + OFF_W2LO + n * PITCH + k * 2) = lv;
    }
    __syncthreads();

    float coef = 1.f + epsp[0];
    int bid = blockIdx.x, G = gridDim.x;
    int nt_mine = (bid < T) ? (T - bid + G - 1) / G : 0;

    char* Hw = sm + OFF_H + wid * 17408;

    // gather 16 edges (this warp's rows) of `tile` into buffer `buf`
    auto gather = [&](int tile, int buf) {
        int ebase = tile * 128 + wid * 16;
        int r = 0, c = 0;
        if (lane < 16) {
            int e = ebase + lane;
            if (e < E) { r = ei[e]; c = ei[E + e]; }
            if (r < 0) r = 0; if (r >= N) r = N - 1;
            if (c < 0) c = 0; if (c >= N) c = N - 1;
        }
        int m = lane >> 1, half = lane & 1;
        int rm = __shfl_sync(0xffffffffu, r, m);
        int cm = __shfl_sync(0xffffffffu, c, m);
        const float* yr = g_y + (long)rm * YPITCH;
        const float* yc = g_y + (long)cm * YPITCH;
        char* dh = Hw + buf * 8704;
        char* dl = dh + 4352;
        int mrow = m * PITCH;
        int rot = (lane * 5) & 15;
#pragma unroll
        for (int i = 0; i < 16; i++) {
            int iie = (i + rot) & 15;
            int k = half * 64 + iie * 4;
            float4 a = *(const float4*)(yr + k);
            float4 b = *(const float4*)(yc + k);
            float4 bb = *(const float4*)(b1s + k);
            float h0 = fmaxf(fmaf(coef, a.x, b.x) + bb.x, 0.f);
            float h1 = fmaxf(fmaf(coef, a.y, b.y) + bb.y, 0.f);
            float h2 = fmaxf(fmaf(coef, a.z, b.z) + bb.z, 0.f);
            float h3 = fmaxf(fmaf(coef, a.w, b.w) + bb.w, 0.f);
            __nv_bfloat16 g0 = __float2bfloat16(h0), g1 = __float2bfloat16(h1);
            __nv_bfloat16 g2 = __float2bfloat16(h2), g3 = __float2bfloat16(h3);
            __nv_bfloat16 l0 = __float2bfloat16(h0 - __bfloat162float(g0));
            __nv_bfloat16 l1 = __float2bfloat16(h1 - __bfloat162float(g1));
            __nv_bfloat16 l2 = __float2bfloat16(h2 - __bfloat162float(g2));
            __nv_bfloat16 l3 = __float2bfloat16(h3 - __bfloat162float(g3));
            __nv_bfloat162 hA = __halves2bfloat162(g0, g1), hB = __halves2bfloat162(g2, g3);
            __nv_bfloat162 lA = __halves2bfloat162(l0, l1), lB = __halves2bfloat162(l2, l3);
            int off = mrow + k * 2;
            *(uint2*)(dh + off) = make_uint2(*(uint32_t*)&hA, *(uint32_t*)&hB);
            *(uint2*)(dl + off) = make_uint2(*(uint32_t*)&lA, *(uint32_t*)&lB);
        }
        __syncwarp();
    };

    // ldmatrix lane address offsets (within a tile base)
    uint32_t a_off = (uint32_t)(((lane & 7) + 8 * ((lane >> 3) & 1)) * PITCH + ((lane >> 4) & 1) * 16);
    uint32_t b_off = (uint32_t)((8 * ((lane >> 4) & 1) + (lane & 7)) * PITCH + ((lane >> 3) & 1) * 16);
    uint32_t w2hi_b = sb + OFF_W2HI + b_off;
    uint32_t w2lo_b = sb + OFF_W2LO + b_off;

    if (nt_mine > 0) gather(bid, 0);

    for (int j = 0; j < nt_mine; j++) {
        int cur = j & 1;
        int tile = bid + j * G;

        // prefetch-gather next tile into other buffer (other warps overlap w/ MMA)
        if (j + 1 < nt_mine) gather(tile + G, 1 - cur);

        // ---- GEMM: 16 rows x 128 cols, K=128, 3-term bf16 split ----
        float acc[16][4];
        int cq = (lane & 3) * 2;
#pragma unroll
        for (int nt = 0; nt < 16; nt++) {
            float2 bv = *(const float2*)(b2s + nt * 8 + cq);
            acc[nt][0] = bv.x; acc[nt][1] = bv.y;
            acc[nt][2] = bv.x; acc[nt][3] = bv.y;
        }
        uint32_t ah_b = sb + OFF_H + (uint32_t)wid * 17408u + (uint32_t)cur * 8704u + a_off;
        uint32_t al_b = ah_b + 4352u;

#pragma unroll
        for (int ks = 0; ks < 8; ks++) {
            uint32_t koff = (uint32_t)ks * 32u;
            uint32_t ah[4], al[4];
            LDSM_X4(ah[0], ah[1], ah[2], ah[3], ah_b + koff);
            LDSM_X4(al[0], al[1], al[2], al[3], al_b + koff);
#pragma unroll
            for (int p = 0; p < 8; p++) {
                uint32_t poff = (uint32_t)p * (16u * PITCH) + koff;
                uint32_t bh0, bh1, bh2, bh3, bl0, bl1, bl2, bl3;
                LDSM_X4(bh0, bh1, bh2, bh3, w2hi_b + poff);
                LDSM_X4(bl0, bl1, bl2, bl3, w2lo_b + poff);
                mma16816(acc[2 * p],     ah, bh0, bh1);
                mma16816(acc[2 * p],     ah, bl0, bl1);
                mma16816(acc[2 * p],     al, bh0, bh1);
                mma16816(acc[2 * p + 1], ah, bh2, bh3);
                mma16816(acc[2 * p + 1], ah, bl2, bl3);
                mma16816(acc[2 * p + 1], al, bh2, bh3);
            }
        }

        // ---- epilogue: direct guarded stores (no cross-warp sync) ----
        int g = lane >> 2;
        int e0row = tile * 128 + wid * 16 + g;
        int e1row = e0row + 8;
        bool v0 = e0row < E, v1 = e1row < E;
        float* o0 = out + (long)e0row * OUT_CH;
        float* o1 = out + (long)e1row * OUT_CH;
#pragma unroll
        for (int nt = 0; nt < 16; nt++) {
            int n0 = nt * 8 + cq;
            if (n0 < OUT_CH) {
                if (v0) o0[n0] = acc[nt][0];
                if (v1) o1[n0] = acc[nt][2];
                if (n0 + 1 < OUT_CH) {
                    if (v0) o0[n0 + 1] = acc[nt][1];
                    if (v1) o1[n0 + 1] = acc[nt][3];
                }
            }
        }
    }
}

extern "C" void kernel_launch(void* const* d_in, const int* in_sizes, int n_in,
                              void* d_out, int out_size) {
    const float* x   = (const float*)d_in[0];
    const int*   ei  = (const int*)d_in[1];
    const float* W1  = (const float*)d_in[2];
    const float* b1  = (const float*)d_in[3];
    const float* W2  = (const float*)d_in[4];
    const float* b2  = (const float*)d_in[5];
    const float* eps = (const float*)d_in[6];
    float* out = (float*)d_out;

    int N = in_sizes[0] / IN_CH;
    int E = in_sizes[1] / 2;
    int T = (E + 127) / 128;

    size_t smA = (size_t)(IN_CH * 132 + IN_CH * 128) * sizeof(float);
    cudaFuncSetAttribute(node_gemm, cudaFuncAttributeMaxDynamicSharedMemorySize, (int)smA);
    cudaFuncSetAttribute(edge_mma, cudaFuncAttributeMaxDynamicSharedMemorySize, SMEM_EDGE);

    node_gemm<<<(N + 127) / 128, 256, smA>>>(x, W1, N);

    int grid = 148; if (grid > T) grid = T;
    edge_mma<<<grid, 256, SMEM_EDGE>>>(ei, b1, W2, b2, eps, out, E, N, T);
}

// round 6
// speedup vs baseline: 1.9124x; 1.4211x over previous
#include <cuda_runtime.h>
#include <cuda_bf16.h>
#include <cstdint>

#define IN_CH 50
#define OUT_CH 121
#define YPITCH 128
#define MAX_N 100000

__device__ __align__(16) float g_y[MAX_N * YPITCH];

// ---------------------------------------------------------------------------
// helpers
// ---------------------------------------------------------------------------
__device__ __forceinline__ uint32_t smem_u32(const void* p) {
    uint32_t a;
    asm("{ .reg .u64 t; cvta.to.shared.u64 t, %1; cvt.u32.u64 %0, t; }" : "=r"(a) : "l"(p));
    return a;
}

#define LDSM_X4(r0, r1, r2, r3, a) \
    asm volatile("ldmatrix.sync.aligned.m8n8.x4.shared.b16 {%0,%1,%2,%3}, [%4];" \
                 : "=r"(r0), "=r"(r1), "=r"(r2), "=r"(r3) : "r"(a))

__device__ __forceinline__ void mma16816(float* c, const uint32_t* a, uint32_t b0, uint32_t b1) {
    asm volatile(
        "mma.sync.aligned.m16n8k16.row.col.f32.bf16.bf16.f32 "
        "{%0,%1,%2,%3}, {%4,%5,%6,%7}, {%8,%9}, {%0,%1,%2,%3};"
        : "+f"(c[0]), "+f"(c[1]), "+f"(c[2]), "+f"(c[3])
        : "r"(a[0]), "r"(a[1]), "r"(a[2]), "r"(a[3]), "r"(b0), "r"(b1));
}

// FFMA2 helpers (node kernel)
__device__ __forceinline__ void fma2(unsigned long long &d, unsigned long long a, unsigned long long b) {
    asm("fma.rn.f32x2 %0, %1, %2, %0;" : "+l"(d) : "l"(a), "l"(b));
}
__device__ __forceinline__ unsigned long long pack2(float x, float y) {
    unsigned long long r; asm("mov.b64 %0, {%1, %2};" : "=l"(r) : "f"(x), "f"(y)); return r;
}
__device__ __forceinline__ float2 unpack2(unsigned long long v) {
    float2 r; asm("mov.b64 {%0, %1}, %2;" : "=f"(r.x), "=f"(r.y) : "l"(v)); return r;
}

// ============================================================================
// Kernel A: Y[N,128] = X[N,50] @ W1[50,121], zero-padded cols (validated R2)
// ============================================================================
__global__ void __launch_bounds__(256, 1) node_gemm(const float* __restrict__ x,
                                                    const float* __restrict__ W1,
                                                    int N) {
    extern __shared__ float sm[];
    float* Xs  = sm;
    float* W1s = Xs + IN_CH * 132;

    int tid = threadIdx.x;
    int e0 = blockIdx.x * 128;

    for (int i = tid; i < 128 * IN_CH; i += 256) {
        int m = i / IN_CH, k = i - m * IN_CH;
        int node = e0 + m;
        Xs[k * 132 + m] = (node < N) ? x[(long)node * IN_CH + k] : 0.f;
    }
    for (int i = tid; i < IN_CH * 128; i += 256) {
        int k = i >> 7, n = i & 127;
        W1s[i] = (n < OUT_CH) ? W1[k * OUT_CH + n] : 0.f;
    }
    __syncthreads();

    int tx = tid & 15, ty = tid >> 4;
    unsigned long long acc[8][4];
#pragma unroll
    for (int i = 0; i < 8; i++)
#pragma unroll
        for (int j = 0; j < 4; j++) acc[i][j] = 0ULL;

    const float* ap  = Xs + ty * 8;
    const float* bp0 = W1s + tx * 4;
    const float* bp1 = W1s + 64 + tx * 4;

#pragma unroll 5
    for (int k = 0; k < IN_CH; k++) {
        float4 a0 = *(const float4*)(ap + k * 132);
        float4 a1 = *(const float4*)(ap + k * 132 + 4);
        float4 b0 = *(const float4*)(bp0 + k * 128);
        float4 b1 = *(const float4*)(bp1 + k * 128);
        unsigned long long bb0 = pack2(b0.x, b0.y);
        unsigned long long bb1 = pack2(b0.z, b0.w);
        unsigned long long bb2 = pack2(b1.x, b1.y);
        unsigned long long bb3 = pack2(b1.z, b1.w);
        float am[8] = {a0.x, a0.y, a0.z, a0.w, a1.x, a1.y, a1.z, a1.w};
#pragma unroll
        for (int i = 0; i < 8; i++) {
            unsigned long long aa = pack2(am[i], am[i]);
            fma2(acc[i][0], aa, bb0);
            fma2(acc[i][1], aa, bb1);
            fma2(acc[i][2], aa, bb2);
            fma2(acc[i][3], aa, bb3);
        }
    }

#pragma unroll
    for (int i = 0; i < 8; i++) {
        int node = e0 + ty * 8 + i;
        if (node < N) {
            float2 v0 = unpack2(acc[i][0]);
            float2 v1 = unpack2(acc[i][1]);
            float2 v2 = unpack2(acc[i][2]);
            float2 v3 = unpack2(acc[i][3]);
            *(float4*)(g_y + (long)node * YPITCH + tx * 4)      = make_float4(v0.x, v0.y, v1.x, v1.y);
            *(float4*)(g_y + (long)node * YPITCH + 64 + tx * 4) = make_float4(v2.x, v2.y, v3.x, v3.y);
        }
    }
}

// ============================================================================
// Kernel B: persistent bf16x3-split mma.sync edge GEMM, 512 threads.
// 16 warps = 8 row-groups (16 edges each) x 2 col-halves (64 cols each).
// smem (from 1KB-aligned base), row pitch 272B:
//   W2hi [128n][272B] @ 0 (34816) ; W2lo @ 34816
//   H: buf b (0/1), rowgroup rg: @ 69632 + b*69632 + rg*8704  (hi 16x272, lo +4352)
//   b1s @ 208896, b2s @ 209408
// ============================================================================
#define PITCH 272
#define OFF_W2HI 0
#define OFF_W2LO 34816
#define OFF_H    69632
#define HBUF     69632
#define OFF_B1   208896
#define OFF_B2   209408
#define SMEM_EDGE (209920 + 1024)

__global__ void __launch_bounds__(512, 1) edge_mma(const int* __restrict__ ei,
                                                   const float* __restrict__ b1,
                                                   const float* __restrict__ W2,
                                                   const float* __restrict__ b2,
                                                   const float* __restrict__ epsp,
                                                   float* __restrict__ out,
                                                   int E, int N, int T) {
    extern __shared__ char smraw[];
    char* sm = (char*)(((uintptr_t)smraw + 1023) & ~(uintptr_t)1023);
    uint32_t sb = smem_u32(sm);

    float* b1s = (float*)(sm + OFF_B1);
    float* b2s = (float*)(sm + OFF_B2);

    int tid = threadIdx.x, wid = tid >> 5, lane = tid & 31;
    int rg = wid >> 1, ch = wid & 1;

    // ---- one-time: W2 split into bf16 hi/lo, [n][k] padded rows; biases ----
    if (tid < 128) {
        b1s[tid] = (tid < OUT_CH) ? b1[tid] : 0.f;
        b2s[tid] = (tid < OUT_CH) ? b2[tid] : 0.f;
    }
    for (int i = tid; i < 128 * 128; i += 512) {
        int n = i >> 7, k = i & 127;
        float v = (n < OUT_CH && k < OUT_CH) ? W2[k * OUT_CH + n] : 0.f;
        __nv_bfloat16 hv = __float2bfloat16(v);
        __nv_bfloat16 lv = __float2bfloat16(v - __bfloat162float(hv));
        *(__nv_bfloat16*)(sm + OFF_W2HI + n * PITCH + k * 2) = hv;
        *(__nv_bfloat16*)(sm + OFF_W2LO + n * PITCH + k * 2) = lv;
    }
    __syncthreads();

    float coef = 1.f + epsp[0];
    int bid = blockIdx.x, G = gridDim.x;
    int nt_mine = (bid < T) ? (T - bid + G - 1) / G : 0;

    // ---- gather: this warp fills 8 rows of its rowgroup into buffer `buf`.
    // lane: row r8 = lane>>2 (0..7), k-part = lane&3 (4 float4 chunks strided 16)
    int m_local = ch * 8 + (lane >> 2);     // row within rowgroup [0..15]
    int m_tile  = rg * 16 + m_local;        // row within 128-edge tile
    int kpart   = (lane & 3) * 4;
    char* Hrg_base = sm + OFF_H + rg * 8704 + m_local * PITCH;

    auto gather = [&](int tile, int buf) {
        int e = tile * 128 + m_tile;
        int r = 0, c = 0;
        if (e < E) { r = ei[e]; c = ei[E + e]; }
        if (r < 0) r = 0; if (r >= N) r = N - 1;
        if (c < 0) c = 0; if (c >= N) c = N - 1;
        const float* yr = g_y + (long)r * YPITCH;
        const float* yc = g_y + (long)c * YPITCH;
        char* dh = Hrg_base + buf * HBUF;
        char* dl = dh + 4352;
#pragma unroll
        for (int i = 0; i < 8; i++) {
            int k = i * 16 + kpart;
            float4 a = *(const float4*)(yr + k);
            float4 b = *(const float4*)(yc + k);
            float4 bb = *(const float4*)(b1s + k);
            float h0 = fmaxf(fmaf(coef, a.x, b.x) + bb.x, 0.f);
            float h1 = fmaxf(fmaf(coef, a.y, b.y) + bb.y, 0.f);
            float h2 = fmaxf(fmaf(coef, a.z, b.z) + bb.z, 0.f);
            float h3 = fmaxf(fmaf(coef, a.w, b.w) + bb.w, 0.f);
            __nv_bfloat16 g0 = __float2bfloat16(h0), g1 = __float2bfloat16(h1);
            __nv_bfloat16 g2 = __float2bfloat16(h2), g3 = __float2bfloat16(h3);
            __nv_bfloat16 l0 = __float2bfloat16(h0 - __bfloat162float(g0));
            __nv_bfloat16 l1 = __float2bfloat16(h1 - __bfloat162float(g1));
            __nv_bfloat16 l2 = __float2bfloat16(h2 - __bfloat162float(g2));
            __nv_bfloat16 l3 = __float2bfloat16(h3 - __bfloat162float(g3));
            __nv_bfloat162 hA = __halves2bfloat162(g0, g1), hB = __halves2bfloat162(g2, g3);
            __nv_bfloat162 lA = __halves2bfloat162(l0, l1), lB = __halves2bfloat162(l2, l3);
            *(uint2*)(dh + k * 2) = make_uint2(*(uint32_t*)&hA, *(uint32_t*)&hB);
            *(uint2*)(dl + k * 2) = make_uint2(*(uint32_t*)&lA, *(uint32_t*)&lB);
        }
    };

    // ldmatrix lane offsets (same fragment math as validated R4)
    uint32_t a_off = (uint32_t)(((lane & 7) + 8 * ((lane >> 3) & 1)) * PITCH + ((lane >> 4) & 1) * 16);
    uint32_t b_off = (uint32_t)((8 * ((lane >> 4) & 1) + (lane & 7)) * PITCH + ((lane >> 3) & 1) * 16);
    uint32_t w2hi_b = sb + OFF_W2HI + (uint32_t)(ch * 64) * PITCH + b_off;
    uint32_t w2lo_b = sb + OFF_W2LO + (uint32_t)(ch * 64) * PITCH + b_off;
    uint32_t aA_base = sb + OFF_H + (uint32_t)rg * 8704u + a_off;

    int cq = (lane & 3) * 2;

    if (nt_mine > 0) gather(bid, 0);
    __syncthreads();

    for (int j = 0; j < nt_mine; j++) {
        int cur = j & 1;
        int tile = bid + j * G;

        // prefetch-gather next tile into alternate buffer (overlaps MMA below)
        if (j + 1 < nt_mine) gather(tile + G, 1 - cur);

        // ---- GEMM: 16 rows x 64 cols, K=128, 3-term bf16 split ----
        float acc[8][4];
#pragma unroll
        for (int t = 0; t < 8; t++) {
            float2 bv = *(const float2*)(b2s + ch * 64 + t * 8 + cq);
            acc[t][0] = bv.x; acc[t][1] = bv.y;
            acc[t][2] = bv.x; acc[t][3] = bv.y;
        }
        uint32_t ah_b = aA_base + (uint32_t)cur * (uint32_t)HBUF;
        uint32_t al_b = ah_b + 4352u;

#pragma unroll
        for (int ks = 0; ks < 8; ks++) {
            uint32_t koff = (uint32_t)ks * 32u;
            uint32_t ah[4], al[4];
            LDSM_X4(ah[0], ah[1], ah[2], ah[3], ah_b + koff);
            LDSM_X4(al[0], al[1], al[2], al[3], al_b + koff);
#pragma unroll
            for (int pp = 0; pp < 2; pp++) {
                uint32_t p0 = (uint32_t)(pp * 2) * (16u * PITCH) + koff;
                uint32_t p1 = p0 + 16u * PITCH;
                uint32_t bh0, bh1, bh2, bh3, bh4, bh5, bh6, bh7;
                uint32_t bl0, bl1, bl2, bl3, bl4, bl5, bl6, bl7;
                LDSM_X4(bh0, bh1, bh2, bh3, w2hi_b + p0);
                LDSM_X4(bh4, bh5, bh6, bh7, w2hi_b + p1);
                LDSM_X4(bl0, bl1, bl2, bl3, w2lo_b + p0);
                LDSM_X4(bl4, bl5, bl6, bl7, w2lo_b + p1);
                float* a0 = acc[pp * 4 + 0];
                float* a1 = acc[pp * 4 + 1];
                float* a2 = acc[pp * 4 + 2];
                float* a3 = acc[pp * 4 + 3];
                // term-major: same-acc dependency distance = 4
                mma16816(a0, ah, bh0, bh1);
                mma16816(a1, ah, bh2, bh3);
                mma16816(a2, ah, bh4, bh5);
                mma16816(a3, ah, bh6, bh7);
                mma16816(a0, ah, bl0, bl1);
                mma16816(a1, ah, bl2, bl3);
                mma16816(a2, ah, bl4, bl5);
                mma16816(a3, ah, bl6, bl7);
                mma16816(a0, al, bh0, bh1);
                mma16816(a1, al, bh2, bh3);
                mma16816(a2, al, bh4, bh5);
                mma16816(a3, al, bh6, bh7);
            }
        }

        // ---- epilogue: direct guarded SCALAR stores (out rows are 121 floats;
        // odd row => odd word offset, so 64-bit stores would be misaligned) ----
        int e0row = tile * 128 + rg * 16 + (lane >> 2);
        int e1row = e0row + 8;
        bool v0 = e0row < E, v1 = e1row < E;
        float* o0 = out + (long)e0row * OUT_CH;
        float* o1 = out + (long)e1row * OUT_CH;
#pragma unroll
        for (int t = 0; t < 8; t++) {
            int n0 = ch * 64 + t * 8 + cq;
            if (n0 < OUT_CH) {
                if (v0) o0[n0] = acc[t][0];
                if (v1) o1[n0] = acc[t][2];
                if (n0 + 1 < OUT_CH) {
                    if (v0) o0[n0 + 1] = acc[t][1];
                    if (v1) o1[n0 + 1] = acc[t][3];
                }
            }
        }
        __syncthreads();
    }
}

extern "C" void kernel_launch(void* const* d_in, const int* in_sizes, int n_in,
                              void* d_out, int out_size) {
    const float* x   = (const float*)d_in[0];
    const int*   ei  = (const int*)d_in[1];
    const float* W1  = (const float*)d_in[2];
    const float* b1  = (const float*)d_in[3];
    const float* W2  = (const float*)d_in[4];
    const float* b2  = (const float*)d_in[5];
    const float* eps = (const float*)d_in[6];
    float* out = (float*)d_out;

    int N = in_sizes[0] / IN_CH;
    int E = in_sizes[1] / 2;
    int T = (E + 127) / 128;

    size_t smA = (size_t)(IN_CH * 132 + IN_CH * 128) * sizeof(float);
    cudaFuncSetAttribute(node_gemm, cudaFuncAttributeMaxDynamicSharedMemorySize, (int)smA);
    cudaFuncSetAttribute(edge_mma, cudaFuncAttributeMaxDynamicSharedMemorySize, SMEM_EDGE);

    node_gemm<<<(N + 127) / 128, 256, smA>>>(x, W1, N);

    int grid = 148; if (grid > T) grid = T;
    edge_mma<<<grid, 512, SMEM_EDGE>>>(ei, b1, W2, b2, eps, out, E, N, T);
}

// round 7
// speedup vs baseline: 2.5026x; 1.3086x over previous
#include <cuda_runtime.h>
#include <cuda_bf16.h>
#include <cstdint>

#define IN_CH 50
#define OUT_CH 121
#define YPITCH 128
#define MAX_N 100000

__device__ __align__(16) float g_y[MAX_N * YPITCH];

// ---------------------------------------------------------------------------
// helpers
// ---------------------------------------------------------------------------
__device__ __forceinline__ uint32_t smem_u32(const void* p) {
    uint32_t a;
    asm("{ .reg .u64 t; cvta.to.shared.u64 t, %1; cvt.u32.u64 %0, t; }" : "=r"(a) : "l"(p));
    return a;
}

#define LDSM_X4(r0, r1, r2, r3, a) \
    asm volatile("ldmatrix.sync.aligned.m8n8.x4.shared.b16 {%0,%1,%2,%3}, [%4];" \
                 : "=r"(r0), "=r"(r1), "=r"(r2), "=r"(r3) : "r"(a))

// pairwise named barrier: 2 warps (64 threads), ids 1..8
#define BAR_PAIR(id) asm volatile("bar.sync %0, 64;" :: "r"(id) : "memory")

__device__ __forceinline__ void mma16816(float* c, const uint32_t* a, uint32_t b0, uint32_t b1) {
    asm volatile(
        "mma.sync.aligned.m16n8k16.row.col.f32.bf16.bf16.f32 "
        "{%0,%1,%2,%3}, {%4,%5,%6,%7}, {%8,%9}, {%0,%1,%2,%3};"
        : "+f"(c[0]), "+f"(c[1]), "+f"(c[2]), "+f"(c[3])
        : "r"(a[0]), "r"(a[1]), "r"(a[2]), "r"(a[3]), "r"(b0), "r"(b1));
}

// FFMA2 helpers (node kernel)
__device__ __forceinline__ void fma2(unsigned long long &d, unsigned long long a, unsigned long long b) {
    asm("fma.rn.f32x2 %0, %1, %2, %0;" : "+l"(d) : "l"(a), "l"(b));
}
__device__ __forceinline__ unsigned long long pack2(float x, float y) {
    unsigned long long r; asm("mov.b64 %0, {%1, %2};" : "=l"(r) : "f"(x), "f"(y)); return r;
}
__device__ __forceinline__ float2 unpack2(unsigned long long v) {
    float2 r; asm("mov.b64 {%0, %1}, %2;" : "=f"(r.x), "=f"(r.y) : "l"(v)); return r;
}

// ============================================================================
// Kernel A: Y[N,128] = X[N,50] @ W1[50,121], zero-padded cols (validated R2)
// ============================================================================
__global__ void __launch_bounds__(256, 1) node_gemm(const float* __restrict__ x,
                                                    const float* __restrict__ W1,
                                                    int N) {
    extern __shared__ float sm[];
    float* Xs  = sm;
    float* W1s = Xs + IN_CH * 132;

    int tid = threadIdx.x;
    int e0 = blockIdx.x * 128;

    for (int i = tid; i < 128 * IN_CH; i += 256) {
        int m = i / IN_CH, k = i - m * IN_CH;
        int node = e0 + m;
        Xs[k * 132 + m] = (node < N) ? x[(long)node * IN_CH + k] : 0.f;
    }
    for (int i = tid; i < IN_CH * 128; i += 256) {
        int k = i >> 7, n = i & 127;
        W1s[i] = (n < OUT_CH) ? W1[k * OUT_CH + n] : 0.f;
    }
    __syncthreads();

    int tx = tid & 15, ty = tid >> 4;
    unsigned long long acc[8][4];
#pragma unroll
    for (int i = 0; i < 8; i++)
#pragma unroll
        for (int j = 0; j < 4; j++) acc[i][j] = 0ULL;

    const float* ap  = Xs + ty * 8;
    const float* bp0 = W1s + tx * 4;
    const float* bp1 = W1s + 64 + tx * 4;

#pragma unroll 5
    for (int k = 0; k < IN_CH; k++) {
        float4 a0 = *(const float4*)(ap + k * 132);
        float4 a1 = *(const float4*)(ap + k * 132 + 4);
        float4 b0 = *(const float4*)(bp0 + k * 128);
        float4 b1 = *(const float4*)(bp1 + k * 128);
        unsigned long long bb0 = pack2(b0.x, b0.y);
        unsigned long long bb1 = pack2(b0.z, b0.w);
        unsigned long long bb2 = pack2(b1.x, b1.y);
        unsigned long long bb3 = pack2(b1.z, b1.w);
        float am[8] = {a0.x, a0.y, a0.z, a0.w, a1.x, a1.y, a1.z, a1.w};
#pragma unroll
        for (int i = 0; i < 8; i++) {
            unsigned long long aa = pack2(am[i], am[i]);
            fma2(acc[i][0], aa, bb0);
            fma2(acc[i][1], aa, bb1);
            fma2(acc[i][2], aa, bb2);
            fma2(acc[i][3], aa, bb3);
        }
    }

#pragma unroll
    for (int i = 0; i < 8; i++) {
        int node = e0 + ty * 8 + i;
        if (node < N) {
            float2 v0 = unpack2(acc[i][0]);
            float2 v1 = unpack2(acc[i][1]);
            float2 v2 = unpack2(acc[i][2]);
            float2 v3 = unpack2(acc[i][3]);
            *(float4*)(g_y + (long)node * YPITCH + tx * 4)      = make_float4(v0.x, v0.y, v1.x, v1.y);
            *(float4*)(g_y + (long)node * YPITCH + 64 + tx * 4) = make_float4(v2.x, v2.y, v3.x, v3.y);
        }
    }
}

// ============================================================================
// Kernel B: persistent bf16x3-split mma.sync edge GEMM, 512 threads.
// 16 warps = 8 row-groups (16 edges) x 2 col-halves (64 cols).
// Each warp-pair (rg) free-runs with pairwise named barriers — no CTA-wide
// sync in the main loop, so pairs drift out of phase and gather latency
// hides behind other pairs' MMA issue.
// ============================================================================
#define PITCH 272
#define OFF_W2HI 0
#define OFF_W2LO 34816
#define OFF_H    69632
#define HBUF     69632
#define OFF_B1   208896
#define OFF_B2   209408
#define SMEM_EDGE (209920 + 1024)

__global__ void __launch_bounds__(512, 1) edge_mma(const int* __restrict__ ei,
                                                   const float* __restrict__ b1,
                                                   const float* __restrict__ W2,
                                                   const float* __restrict__ b2,
                                                   const float* __restrict__ epsp,
                                                   float* __restrict__ out,
                                                   int E, int N, int T) {
    extern __shared__ char smraw[];
    char* sm = (char*)(((uintptr_t)smraw + 1023) & ~(uintptr_t)1023);
    uint32_t sb = smem_u32(sm);

    float* b1s = (float*)(sm + OFF_B1);
    float* b2s = (float*)(sm + OFF_B2);

    int tid = threadIdx.x, wid = tid >> 5, lane = tid & 31;
    int rg = wid >> 1, ch = wid & 1;
    int barid = rg + 1;   // named barrier ids 1..8

    // ---- one-time: W2 split into bf16 hi/lo, [n][k] padded rows; biases ----
    if (tid < 128) {
        b1s[tid] = (tid < OUT_CH) ? b1[tid] : 0.f;
        b2s[tid] = (tid < OUT_CH) ? b2[tid] : 0.f;
    }
    for (int i = tid; i < 128 * 128; i += 512) {
        int n = i >> 7, k = i & 127;
        float v = (n < OUT_CH && k < OUT_CH) ? W2[k * OUT_CH + n] : 0.f;
        __nv_bfloat16 hv = __float2bfloat16(v);
        __nv_bfloat16 lv = __float2bfloat16(v - __bfloat162float(hv));
        *(__nv_bfloat16*)(sm + OFF_W2HI + n * PITCH + k * 2) = hv;
        *(__nv_bfloat16*)(sm + OFF_W2LO + n * PITCH + k * 2) = lv;
    }
    __syncthreads();   // last CTA-wide sync: W2/biases are read-only after this

    float coef = 1.f + epsp[0];
    int bid = blockIdx.x, G = gridDim.x;
    int nt_mine = (bid < T) ? (T - bid + G - 1) / G : 0;

    // ---- gather: this warp fills its 8 rows of rowgroup rg into buffer `buf`
    int m_local = ch * 8 + (lane >> 2);     // row within rowgroup [0..15]
    int m_tile  = rg * 16 + m_local;        // row within 128-edge tile
    int kpart   = (lane & 3) * 4;
    char* Hrg_base = sm + OFF_H + rg * 8704 + m_local * PITCH;

    auto gather = [&](int tile, int buf) {
        int e = tile * 128 + m_tile;
        int r = 0, c = 0;
        if (e < E) { r = ei[e]; c = ei[E + e]; }
        if (r < 0) r = 0; if (r >= N) r = N - 1;
        if (c < 0) c = 0; if (c >= N) c = N - 1;
        const float* yr = g_y + (long)r * YPITCH;
        const float* yc = g_y + (long)c * YPITCH;
        char* dh = Hrg_base + buf * HBUF;
        char* dl = dh + 4352;
#pragma unroll
        for (int i = 0; i < 8; i++) {
            int k = i * 16 + kpart;
            float4 a = *(const float4*)(yr + k);
            float4 b = *(const float4*)(yc + k);
            float4 bb = *(const float4*)(b1s + k);
            float h0 = fmaxf(fmaf(coef, a.x, b.x) + bb.x, 0.f);
            float h1 = fmaxf(fmaf(coef, a.y, b.y) + bb.y, 0.f);
            float h2 = fmaxf(fmaf(coef, a.z, b.z) + bb.z, 0.f);
            float h3 = fmaxf(fmaf(coef, a.w, b.w) + bb.w, 0.f);
            __nv_bfloat16 g0 = __float2bfloat16(h0), g1 = __float2bfloat16(h1);
            __nv_bfloat16 g2 = __float2bfloat16(h2), g3 = __float2bfloat16(h3);
            __nv_bfloat16 l0 = __float2bfloat16(h0 - __bfloat162float(g0));
            __nv_bfloat16 l1 = __float2bfloat16(h1 - __bfloat162float(g1));
            __nv_bfloat16 l2 = __float2bfloat16(h2 - __bfloat162float(g2));
            __nv_bfloat16 l3 = __float2bfloat16(h3 - __bfloat162float(g3));
            __nv_bfloat162 hA = __halves2bfloat162(g0, g1), hB = __halves2bfloat162(g2, g3);
            __nv_bfloat162 lA = __halves2bfloat162(l0, l1), lB = __halves2bfloat162(l2, l3);
            *(uint2*)(dh + k * 2) = make_uint2(*(uint32_t*)&hA, *(uint32_t*)&hB);
            *(uint2*)(dl + k * 2) = make_uint2(*(uint32_t*)&lA, *(uint32_t*)&lB);
        }
    };

    // ldmatrix lane offsets (validated fragment math)
    uint32_t a_off = (uint32_t)(((lane & 7) + 8 * ((lane >> 3) & 1)) * PITCH + ((lane >> 4) & 1) * 16);
    uint32_t b_off = (uint32_t)((8 * ((lane >> 4) & 1) + (lane & 7)) * PITCH + ((lane >> 3) & 1) * 16);
    uint32_t w2hi_b = sb + OFF_W2HI + (uint32_t)(ch * 64) * PITCH + b_off;
    uint32_t w2lo_b = sb + OFF_W2LO + (uint32_t)(ch * 64) * PITCH + b_off;
    uint32_t aA_base = sb + OFF_H + (uint32_t)rg * 8704u + a_off;

    int cq = (lane & 3) * 2;

    if (nt_mine > 0) {
        gather(bid, 0);
        BAR_PAIR(barid);   // buf0 ready for both warps of the pair
    }

    for (int j = 0; j < nt_mine; j++) {
        int cur = j & 1;
        int tile = bid + j * G;

        // (A) gather next tile into alternate buffer
        if (j + 1 < nt_mine) gather(tile + G, 1 - cur);
        // (B) pair barrier: partner's writes to buf[1-cur] visible before
        //     next iteration's MMA; also orders vs. partner's prior reads
        BAR_PAIR(barid);

        // (C) GEMM: 16 rows x 64 cols, K=128, 3-term bf16 split
        float acc[8][4];
#pragma unroll
        for (int t = 0; t < 8; t++) {
            float2 bv = *(const float2*)(b2s + ch * 64 + t * 8 + cq);
            acc[t][0] = bv.x; acc[t][1] = bv.y;
            acc[t][2] = bv.x; acc[t][3] = bv.y;
        }
        uint32_t ah_b = aA_base + (uint32_t)cur * (uint32_t)HBUF;
        uint32_t al_b = ah_b + 4352u;

#pragma unroll
        for (int ks = 0; ks < 8; ks++) {
            uint32_t koff = (uint32_t)ks * 32u;
            uint32_t ah[4], al[4];
            LDSM_X4(ah[0], ah[1], ah[2], ah[3], ah_b + koff);
            LDSM_X4(al[0], al[1], al[2], al[3], al_b + koff);
#pragma unroll
            for (int pp = 0; pp < 2; pp++) {
                uint32_t p0 = (uint32_t)(pp * 2) * (16u * PITCH) + koff;
                uint32_t p1 = p0 + 16u * PITCH;
                uint32_t bh0, bh1, bh2, bh3, bh4, bh5, bh6, bh7;
                uint32_t bl0, bl1, bl2, bl3, bl4, bl5, bl6, bl7;
                LDSM_X4(bh0, bh1, bh2, bh3, w2hi_b + p0);
                LDSM_X4(bh4, bh5, bh6, bh7, w2hi_b + p1);
                LDSM_X4(bl0, bl1, bl2, bl3, w2lo_b + p0);
                LDSM_X4(bl4, bl5, bl6, bl7, w2lo_b + p1);
                float* a0 = acc[pp * 4 + 0];
                float* a1 = acc[pp * 4 + 1];
                float* a2 = acc[pp * 4 + 2];
                float* a3 = acc[pp * 4 + 3];
                mma16816(a0, ah, bh0, bh1);
                mma16816(a1, ah, bh2, bh3);
                mma16816(a2, ah, bh4, bh5);
                mma16816(a3, ah, bh6, bh7);
                mma16816(a0, ah, bl0, bl1);
                mma16816(a1, ah, bl2, bl3);
                mma16816(a2, ah, bl4, bl5);
                mma16816(a3, ah, bl6, bl7);
                mma16816(a0, al, bh0, bh1);
                mma16816(a1, al, bh2, bh3);
                mma16816(a2, al, bh4, bh5);
                mma16816(a3, al, bh6, bh7);
            }
        }

        // epilogue: scalar stores (121-float rows: odd rows break 8B alignment)
        int e0row = tile * 128 + rg * 16 + (lane >> 2);
        int e1row = e0row + 8;
        bool v0 = e0row < E, v1 = e1row < E;
        float* o0 = out + (long)e0row * OUT_CH;
        float* o1 = out + (long)e1row * OUT_CH;
#pragma unroll
        for (int t = 0; t < 8; t++) {
            int n0 = ch * 64 + t * 8 + cq;
            if (n0 < OUT_CH) {
                if (v0) o0[n0] = acc[t][0];
                if (v1) o1[n0] = acc[t][2];
                if (n0 + 1 < OUT_CH) {
                    if (v0) o0[n0 + 1] = acc[t][1];
                    if (v1) o1[n0 + 1] = acc[t][3];
                }
            }
        }

        // (D) pair barrier: both warps done READING buf[cur] before either
        //     overwrites it in the next iteration's gather
        BAR_PAIR(barid);
    }
}

extern "C" void kernel_launch(void* const* d_in, const int* in_sizes, int n_in,
                              void* d_out, int out_size) {
    const float* x   = (const float*)d_in[0];
    const int*   ei  = (const int*)d_in[1];
    const float* W1  = (const float*)d_in[2];
    const float* b1  = (const float*)d_in[3];
    const float* W2  = (const float*)d_in[4];
    const float* b2  = (const float*)d_in[5];
    const float* eps = (const float*)d_in[6];
    float* out = (float*)d_out;

    int N = in_sizes[0] / IN_CH;
    int E = in_sizes[1] / 2;
    int T = (E + 127) / 128;

    size_t smA = (size_t)(IN_CH * 132 + IN_CH * 128) * sizeof(float);
    cudaFuncSetAttribute(node_gemm, cudaFuncAttributeMaxDynamicSharedMemorySize, (int)smA);
    cudaFuncSetAttribute(edge_mma, cudaFuncAttributeMaxDynamicSharedMemorySize, SMEM_EDGE);

    node_gemm<<<(N + 127) / 128, 256, smA>>>(x, W1, N);

    int grid = 148; if (grid > T) grid = T;
    edge_mma<<<grid, 512, SMEM_EDGE>>>(ei, b1, W2, b2, eps, out, E, N, T);
}

// round 8
// speedup vs baseline: 2.7963x; 1.1174x over previous
#include <cuda_runtime.h>
#include <cuda_fp16.h>
#include <cstdint>

#define IN_CH 50
#define OUT_CH 121
#define YPITCH 128
#define MAX_N 100000

__device__ __align__(16) float g_y[MAX_N * YPITCH];

// ---------------------------------------------------------------------------
// helpers
// ---------------------------------------------------------------------------
__device__ __forceinline__ uint32_t smem_u32(const void* p) {
    uint32_t a;
    asm("{ .reg .u64 t; cvta.to.shared.u64 t, %1; cvt.u32.u64 %0, t; }" : "=r"(a) : "l"(p));
    return a;
}

#define LDSM_X4(r0, r1, r2, r3, a) \
    asm volatile("ldmatrix.sync.aligned.m8n8.x4.shared.b16 {%0,%1,%2,%3}, [%4];" \
                 : "=r"(r0), "=r"(r1), "=r"(r2), "=r"(r3) : "r"(a))

// pairwise named barrier: 2 warps (64 threads), ids 1..8
#define BAR_PAIR(id) asm volatile("bar.sync %0, 64;" :: "r"(id) : "memory")

__device__ __forceinline__ void mma16816(float* c, const uint32_t* a, uint32_t b0, uint32_t b1) {
    asm volatile(
        "mma.sync.aligned.m16n8k16.row.col.f32.f16.f16.f32 "
        "{%0,%1,%2,%3}, {%4,%5,%6,%7}, {%8,%9}, {%0,%1,%2,%3};"
        : "+f"(c[0]), "+f"(c[1]), "+f"(c[2]), "+f"(c[3])
        : "r"(a[0]), "r"(a[1]), "r"(a[2]), "r"(a[3]), "r"(b0), "r"(b1));
}

// FFMA2 helpers (node kernel)
__device__ __forceinline__ void fma2(unsigned long long &d, unsigned long long a, unsigned long long b) {
    asm("fma.rn.f32x2 %0, %1, %2, %0;" : "+l"(d) : "l"(a), "l"(b));
}
__device__ __forceinline__ unsigned long long pack2(float x, float y) {
    unsigned long long r; asm("mov.b64 %0, {%1, %2};" : "=l"(r) : "f"(x), "f"(y)); return r;
}
__device__ __forceinline__ float2 unpack2(unsigned long long v) {
    float2 r; asm("mov.b64 {%0, %1}, %2;" : "=f"(r.x), "=f"(r.y) : "l"(v)); return r;
}

// ============================================================================
// Kernel A: Y[N,128] = X[N,50] @ W1[50,121], zero-padded cols (validated R2)
// ============================================================================
__global__ void __launch_bounds__(256, 1) node_gemm(const float* __restrict__ x,
                                                    const float* __restrict__ W1,
                                                    int N) {
    extern __shared__ float sm[];
    float* Xs  = sm;
    float* W1s = Xs + IN_CH * 132;

    int tid = threadIdx.x;
    int e0 = blockIdx.x * 128;

    for (int i = tid; i < 128 * IN_CH; i += 256) {
        int m = i / IN_CH, k = i - m * IN_CH;
        int node = e0 + m;
        Xs[k * 132 + m] = (node < N) ? x[(long)node * IN_CH + k] : 0.f;
    }
    for (int i = tid; i < IN_CH * 128; i += 256) {
        int k = i >> 7, n = i & 127;
        W1s[i] = (n < OUT_CH) ? W1[k * OUT_CH + n] : 0.f;
    }
    __syncthreads();

    int tx = tid & 15, ty = tid >> 4;
    unsigned long long acc[8][4];
#pragma unroll
    for (int i = 0; i < 8; i++)
#pragma unroll
        for (int j = 0; j < 4; j++) acc[i][j] = 0ULL;

    const float* ap  = Xs + ty * 8;
    const float* bp0 = W1s + tx * 4;
    const float* bp1 = W1s + 64 + tx * 4;

#pragma unroll 5
    for (int k = 0; k < IN_CH; k++) {
        float4 a0 = *(const float4*)(ap + k * 132);
        float4 a1 = *(const float4*)(ap + k * 132 + 4);
        float4 b0 = *(const float4*)(bp0 + k * 128);
        float4 b1 = *(const float4*)(bp1 + k * 128);
        unsigned long long bb0 = pack2(b0.x, b0.y);
        unsigned long long bb1 = pack2(b0.z, b0.w);
        unsigned long long bb2 = pack2(b1.x, b1.y);
        unsigned long long bb3 = pack2(b1.z, b1.w);
        float am[8] = {a0.x, a0.y, a0.z, a0.w, a1.x, a1.y, a1.z, a1.w};
#pragma unroll
        for (int i = 0; i < 8; i++) {
            unsigned long long aa = pack2(am[i], am[i]);
            fma2(acc[i][0], aa, bb0);
            fma2(acc[i][1], aa, bb1);
            fma2(acc[i][2], aa, bb2);
            fma2(acc[i][3], aa, bb3);
        }
    }

#pragma unroll
    for (int i = 0; i < 8; i++) {
        int node = e0 + ty * 8 + i;
        if (node < N) {
            float2 v0 = unpack2(acc[i][0]);
            float2 v1 = unpack2(acc[i][1]);
            float2 v2 = unpack2(acc[i][2]);
            float2 v3 = unpack2(acc[i][3]);
            *(float4*)(g_y + (long)node * YPITCH + tx * 4)      = make_float4(v0.x, v0.y, v1.x, v1.y);
            *(float4*)(g_y + (long)node * YPITCH + 64 + tx * 4) = make_float4(v2.x, v2.y, v3.x, v3.y);
        }
    }
}

// ============================================================================
// Kernel B: persistent fp16x2-split mma.sync edge GEMM, 512 threads.
// OUT = (hi(H) + lo(H)) @ fp16(W2): dropped term H*wlo ~ 2^-11 relative.
// 16 warps = 8 row-groups (16 edges) x 2 col-halves (64 cols), pairwise
// named-barrier desync (validated R7).
// smem (from 1KB-aligned base), row pitch 272B:
//   W2 fp16 [128n][272B] @ 0 (34816)
//   H: buf b (0/1), rowgroup rg: @ 34816 + b*69632 + rg*8704 (hi 16x272, lo +4352)
//   b1s @ 174080, b2s @ 174592
// ============================================================================
#define PITCH 272
#define OFF_W2   0
#define OFF_H    34816
#define HBUF     69632
#define OFF_B1   174080
#define OFF_B2   174592
#define SMEM_EDGE (175104 + 1024)

__global__ void __launch_bounds__(512, 1) edge_mma(const int* __restrict__ ei,
                                                   const float* __restrict__ b1,
                                                   const float* __restrict__ W2,
                                                   const float* __restrict__ b2,
                                                   const float* __restrict__ epsp,
                                                   float* __restrict__ out,
                                                   int E, int N, int T) {
    extern __shared__ char smraw[];
    char* sm = (char*)(((uintptr_t)smraw + 1023) & ~(uintptr_t)1023);
    uint32_t sb = smem_u32(sm);

    float* b1s = (float*)(sm + OFF_B1);
    float* b2s = (float*)(sm + OFF_B2);

    int tid = threadIdx.x, wid = tid >> 5, lane = tid & 31;
    int rg = wid >> 1, ch = wid & 1;
    int barid = rg + 1;   // named barrier ids 1..8

    // ---- one-time: W2 -> fp16, [n][k] padded rows; biases ----
    if (tid < 128) {
        b1s[tid] = (tid < OUT_CH) ? b1[tid] : 0.f;
        b2s[tid] = (tid < OUT_CH) ? b2[tid] : 0.f;
    }
    for (int i = tid; i < 128 * 128; i += 512) {
        int n = i >> 7, k = i & 127;
        float v = (n < OUT_CH && k < OUT_CH) ? W2[k * OUT_CH + n] : 0.f;
        *(__half*)(sm + OFF_W2 + n * PITCH + k * 2) = __float2half(v);
    }
    __syncthreads();   // last CTA-wide sync

    float coef = 1.f + epsp[0];
    int bid = blockIdx.x, G = gridDim.x;
    int nt_mine = (bid < T) ? (T - bid + G - 1) / G : 0;

    // ---- gather: this warp fills its 8 rows of rowgroup rg into buffer `buf`
    int m_local = ch * 8 + (lane >> 2);     // row within rowgroup [0..15]
    int m_tile  = rg * 16 + m_local;        // row within 128-edge tile
    int kpart   = (lane & 3) * 4;
    char* Hrg_base = sm + OFF_H + rg * 8704 + m_local * PITCH;

    auto gather = [&](int tile, int buf) {
        int e = tile * 128 + m_tile;
        int r = 0, c = 0;
        if (e < E) { r = ei[e]; c = ei[E + e]; }
        if (r < 0) r = 0; if (r >= N) r = N - 1;
        if (c < 0) c = 0; if (c >= N) c = N - 1;
        const float* yr = g_y + (long)r * YPITCH;
        const float* yc = g_y + (long)c * YPITCH;
        char* dh = Hrg_base + buf * HBUF;
        char* dl = dh + 4352;
#pragma unroll
        for (int i = 0; i < 8; i++) {
            int k = i * 16 + kpart;
            float4 a = *(const float4*)(yr + k);
            float4 b = *(const float4*)(yc + k);
            float4 bb = *(const float4*)(b1s + k);
            float h0 = fmaxf(fmaf(coef, a.x, b.x) + bb.x, 0.f);
            float h1 = fmaxf(fmaf(coef, a.y, b.y) + bb.y, 0.f);
            float h2 = fmaxf(fmaf(coef, a.z, b.z) + bb.z, 0.f);
            float h3 = fmaxf(fmaf(coef, a.w, b.w) + bb.w, 0.f);
            __half g0 = __float2half(h0), g1 = __float2half(h1);
            __half g2 = __float2half(h2), g3 = __float2half(h3);
            __half l0 = __float2half(h0 - __half2float(g0));
            __half l1 = __float2half(h1 - __half2float(g1));
            __half l2 = __float2half(h2 - __half2float(g2));
            __half l3 = __float2half(h3 - __half2float(g3));
            __half2 hA = __halves2half2(g0, g1), hB = __halves2half2(g2, g3);
            __half2 lA = __halves2half2(l0, l1), lB = __halves2half2(l2, l3);
            *(uint2*)(dh + k * 2) = make_uint2(*(uint32_t*)&hA, *(uint32_t*)&hB);
            *(uint2*)(dl + k * 2) = make_uint2(*(uint32_t*)&lA, *(uint32_t*)&lB);
        }
    };

    // ldmatrix lane offsets (validated fragment math)
    uint32_t a_off = (uint32_t)(((lane & 7) + 8 * ((lane >> 3) & 1)) * PITCH + ((lane >> 4) & 1) * 16);
    uint32_t b_off = (uint32_t)((8 * ((lane >> 4) & 1) + (lane & 7)) * PITCH + ((lane >> 3) & 1) * 16);
    uint32_t w2_b = sb + OFF_W2 + (uint32_t)(ch * 64) * PITCH + b_off;
    uint32_t aA_base = sb + OFF_H + (uint32_t)rg * 8704u + a_off;

    int cq = (lane & 3) * 2;

    if (nt_mine > 0) {
        gather(bid, 0);
        BAR_PAIR(barid);   // buf0 ready for both warps of the pair
    }

    for (int j = 0; j < nt_mine; j++) {
        int cur = j & 1;
        int tile = bid + j * G;

        // (A) gather next tile into alternate buffer
        if (j + 1 < nt_mine) gather(tile + G, 1 - cur);
        // (B) pair barrier
        BAR_PAIR(barid);

        // (C) GEMM: 16 rows x 64 cols, K=128, 2-term fp16 split
        float acc[8][4];
#pragma unroll
        for (int t = 0; t < 8; t++) {
            float2 bv = *(const float2*)(b2s + ch * 64 + t * 8 + cq);
            acc[t][0] = bv.x; acc[t][1] = bv.y;
            acc[t][2] = bv.x; acc[t][3] = bv.y;
        }
        uint32_t ah_b = aA_base + (uint32_t)cur * (uint32_t)HBUF;
        uint32_t al_b = ah_b + 4352u;

#pragma unroll
        for (int ks = 0; ks < 8; ks++) {
            uint32_t koff = (uint32_t)ks * 32u;
            uint32_t ah[4], al[4];
            LDSM_X4(ah[0], ah[1], ah[2], ah[3], ah_b + koff);
            LDSM_X4(al[0], al[1], al[2], al[3], al_b + koff);
#pragma unroll
            for (int pp = 0; pp < 2; pp++) {
                uint32_t p0 = (uint32_t)(pp * 2) * (16u * PITCH) + koff;
                uint32_t p1 = p0 + 16u * PITCH;
                uint32_t bh0, bh1, bh2, bh3, bh4, bh5, bh6, bh7;
                LDSM_X4(bh0, bh1, bh2, bh3, w2_b + p0);
                LDSM_X4(bh4, bh5, bh6, bh7, w2_b + p1);
                float* a0 = acc[pp * 4 + 0];
                float* a1 = acc[pp * 4 + 1];
                float* a2 = acc[pp * 4 + 2];
                float* a3 = acc[pp * 4 + 3];
                // term-major: same-acc dependency distance = 4
                mma16816(a0, ah, bh0, bh1);
                mma16816(a1, ah, bh2, bh3);
                mma16816(a2, ah, bh4, bh5);
                mma16816(a3, ah, bh6, bh7);
                mma16816(a0, al, bh0, bh1);
                mma16816(a1, al, bh2, bh3);
                mma16816(a2, al, bh4, bh5);
                mma16816(a3, al, bh6, bh7);
            }
        }

        // epilogue: scalar stores (121-float rows: odd rows break 8B alignment)
        int e0row = tile * 128 + rg * 16 + (lane >> 2);
        int e1row = e0row + 8;
        bool v0 = e0row < E, v1 = e1row < E;
        float* o0 = out + (long)e0row * OUT_CH;
        float* o1 = out + (long)e1row * OUT_CH;
#pragma unroll
        for (int t = 0; t < 8; t++) {
            int n0 = ch * 64 + t * 8 + cq;
            if (n0 < OUT_CH) {
                if (v0) o0[n0] = acc[t][0];
                if (v1) o1[n0] = acc[t][2];
                if (n0 + 1 < OUT_CH) {
                    if (v0) o0[n0 + 1] = acc[t][1];
                    if (v1) o1[n0 + 1] = acc[t][3];
                }
            }
        }

        // (D) pair barrier: both warps done READING buf[cur]
        BAR_PAIR(barid);
    }
}

extern "C" void kernel_launch(void* const* d_in, const int* in_sizes, int n_in,
                              void* d_out, int out_size) {
    const float* x   = (const float*)d_in[0];
    const int*   ei  = (const int*)d_in[1];
    const float* W1  = (const float*)d_in[2];
    const float* b1  = (const float*)d_in[3];
    const float* W2  = (const float*)d_in[4];
    const float* b2  = (const float*)d_in[5];
    const float* eps = (const float*)d_in[6];
    float* out = (float*)d_out;

    int N = in_sizes[0] / IN_CH;
    int E = in_sizes[1] / 2;
    int T = (E + 127) / 128;

    size_t smA = (size_t)(IN_CH * 132 + IN_CH * 128) * sizeof(float);
    cudaFuncSetAttribute(node_gemm, cudaFuncAttributeMaxDynamicSharedMemorySize, (int)smA);
    cudaFuncSetAttribute(edge_mma, cudaFuncAttributeMaxDynamicSharedMemorySize, SMEM_EDGE);

    node_gemm<<<(N + 127) / 128, 256, smA>>>(x, W1, N);

    int grid = 148; if (grid > T) grid = T;
    edge_mma<<<grid, 512, SMEM_EDGE>>>(ei, b1, W2, b2, eps, out, E, N, T);
}

// round 9
// speedup vs baseline: 3.3651x; 1.2034x over previous
#include <cuda_runtime.h>
#include <cuda_fp16.h>
#include <cstdint>

#define IN_CH 50
#define OUT_CH 121
#define YPITCH 128
#define MAX_N 100000

__device__ __align__(16) float g_y[MAX_N * YPITCH];

// ---------------------------------------------------------------------------
// helpers
// ---------------------------------------------------------------------------
__device__ __forceinline__ uint32_t smem_u32(const void* p) {
    uint32_t a;
    asm("{ .reg .u64 t; cvta.to.shared.u64 t, %1; cvt.u32.u64 %0, t; }" : "=r"(a) : "l"(p));
    return a;
}

#define LDSM_X4(r0, r1, r2, r3, a) \
    asm volatile("ldmatrix.sync.aligned.m8n8.x4.shared.b16 {%0,%1,%2,%3}, [%4];" \
                 : "=r"(r0), "=r"(r1), "=r"(r2), "=r"(r3) : "r"(a))

// pairwise named barrier: 2 warps (64 threads), ids 1..8
#define BAR_PAIR(id) asm volatile("bar.sync %0, 64;" :: "r"(id) : "memory")

__device__ __forceinline__ void mma16816(float* c, const uint32_t* a, uint32_t b0, uint32_t b1) {
    asm volatile(
        "mma.sync.aligned.m16n8k16.row.col.f32.f16.f16.f32 "
        "{%0,%1,%2,%3}, {%4,%5,%6,%7}, {%8,%9}, {%0,%1,%2,%3};"
        : "+f"(c[0]), "+f"(c[1]), "+f"(c[2]), "+f"(c[3])
        : "r"(a[0]), "r"(a[1]), "r"(a[2]), "r"(a[3]), "r"(b0), "r"(b1));
}

// FFMA2 helpers (node kernel)
__device__ __forceinline__ void fma2(unsigned long long &d, unsigned long long a, unsigned long long b) {
    asm("fma.rn.f32x2 %0, %1, %2, %0;" : "+l"(d) : "l"(a), "l"(b));
}
__device__ __forceinline__ unsigned long long pack2(float x, float y) {
    unsigned long long r; asm("mov.b64 %0, {%1, %2};" : "=l"(r) : "f"(x), "f"(y)); return r;
}
__device__ __forceinline__ float2 unpack2(unsigned long long v) {
    float2 r; asm("mov.b64 {%0, %1}, %2;" : "=f"(r.x), "=f"(r.y) : "l"(v)); return r;
}

// ============================================================================
// Kernel A: Y[N,128] = X[N,50] @ W1[50,121], zero-padded cols (validated R2)
// ============================================================================
__global__ void __launch_bounds__(256, 1) node_gemm(const float* __restrict__ x,
                                                    const float* __restrict__ W1,
                                                    int N) {
    extern __shared__ float sm[];
    float* Xs  = sm;
    float* W1s = Xs + IN_CH * 132;

    int tid = threadIdx.x;
    int e0 = blockIdx.x * 128;

    for (int i = tid; i < 128 * IN_CH; i += 256) {
        int m = i / IN_CH, k = i - m * IN_CH;
        int node = e0 + m;
        Xs[k * 132 + m] = (node < N) ? x[(long)node * IN_CH + k] : 0.f;
    }
    for (int i = tid; i < IN_CH * 128; i += 256) {
        int k = i >> 7, n = i & 127;
        W1s[i] = (n < OUT_CH) ? W1[k * OUT_CH + n] : 0.f;
    }
    __syncthreads();

    int tx = tid & 15, ty = tid >> 4;
    unsigned long long acc[8][4];
#pragma unroll
    for (int i = 0; i < 8; i++)
#pragma unroll
        for (int j = 0; j < 4; j++) acc[i][j] = 0ULL;

    const float* ap  = Xs + ty * 8;
    const float* bp0 = W1s + tx * 4;
    const float* bp1 = W1s + 64 + tx * 4;

#pragma unroll 5
    for (int k = 0; k < IN_CH; k++) {
        float4 a0 = *(const float4*)(ap + k * 132);
        float4 a1 = *(const float4*)(ap + k * 132 + 4);
        float4 b0 = *(const float4*)(bp0 + k * 128);
        float4 b1 = *(const float4*)(bp1 + k * 128);
        unsigned long long bb0 = pack2(b0.x, b0.y);
        unsigned long long bb1 = pack2(b0.z, b0.w);
        unsigned long long bb2 = pack2(b1.x, b1.y);
        unsigned long long bb3 = pack2(b1.z, b1.w);
        float am[8] = {a0.x, a0.y, a0.z, a0.w, a1.x, a1.y, a1.z, a1.w};
#pragma unroll
        for (int i = 0; i < 8; i++) {
            unsigned long long aa = pack2(am[i], am[i]);
            fma2(acc[i][0], aa, bb0);
            fma2(acc[i][1], aa, bb1);
            fma2(acc[i][2], aa, bb2);
            fma2(acc[i][3], aa, bb3);
        }
    }

#pragma unroll
    for (int i = 0; i < 8; i++) {
        int node = e0 + ty * 8 + i;
        if (node < N) {
            float2 v0 = unpack2(acc[i][0]);
            float2 v1 = unpack2(acc[i][1]);
            float2 v2 = unpack2(acc[i][2]);
            float2 v3 = unpack2(acc[i][3]);
            *(float4*)(g_y + (long)node * YPITCH + tx * 4)      = make_float4(v0.x, v0.y, v1.x, v1.y);
            *(float4*)(g_y + (long)node * YPITCH + 64 + tx * 4) = make_float4(v2.x, v2.y, v3.x, v3.y);
        }
    }
}

// ============================================================================
// Kernel B: persistent fp16x2-split mma.sync edge GEMM, 512 threads,
// gather software-pipelined INTO the MMA loop (chunk s consumed at step s+2),
// ei indices double-prefetched, one pair-barrier per tile.
// ============================================================================
#define PITCH 272
#define OFF_W2   0
#define OFF_H    34816
#define HBUF     69632
#define OFF_B1   174080
#define OFF_B2   174592
#define SMEM_EDGE (175104 + 1024)

__global__ void __launch_bounds__(512, 1) edge_mma(const int* __restrict__ ei,
                                                   const float* __restrict__ b1,
                                                   const float* __restrict__ W2,
                                                   const float* __restrict__ b2,
                                                   const float* __restrict__ epsp,
                                                   float* __restrict__ out,
                                                   int E, int N, int T) {
    extern __shared__ char smraw[];
    char* sm = (char*)(((uintptr_t)smraw + 1023) & ~(uintptr_t)1023);
    uint32_t sb = smem_u32(sm);

    float* b1s = (float*)(sm + OFF_B1);
    float* b2s = (float*)(sm + OFF_B2);

    int tid = threadIdx.x, wid = tid >> 5, lane = tid & 31;
    int rg = wid >> 1, ch = wid & 1;
    int barid = rg + 1;

    // ---- one-time: W2 -> fp16, [n][k] padded rows; biases ----
    if (tid < 128) {
        b1s[tid] = (tid < OUT_CH) ? b1[tid] : 0.f;
        b2s[tid] = (tid < OUT_CH) ? b2[tid] : 0.f;
    }
    for (int i = tid; i < 128 * 128; i += 512) {
        int n = i >> 7, k = i & 127;
        float v = (n < OUT_CH && k < OUT_CH) ? W2[k * OUT_CH + n] : 0.f;
        *(__half*)(sm + OFF_W2 + n * PITCH + k * 2) = __float2half(v);
    }
    __syncthreads();   // last CTA-wide sync

    float coef = 1.f + epsp[0];
    int bid = blockIdx.x, G = gridDim.x;
    int nt_mine = (bid < T) ? (T - bid + G - 1) / G : 0;

    int m_local = ch * 8 + (lane >> 2);     // row within rowgroup [0..15]
    int m_tile  = rg * 16 + m_local;        // row within 128-edge tile
    int kpart   = (lane & 3) * 4;
    char* Hrg_base = sm + OFF_H + rg * 8704 + m_local * PITCH;

    // convert one float4-pair chunk at column k into fp16 hi/lo smem
    auto convert = [&](float4 a, float4 b, int k, char* dh, char* dl) {
        float4 bb = *(const float4*)(b1s + k);
        float h0 = fmaxf(fmaf(coef, a.x, b.x) + bb.x, 0.f);
        float h1 = fmaxf(fmaf(coef, a.y, b.y) + bb.y, 0.f);
        float h2 = fmaxf(fmaf(coef, a.z, b.z) + bb.z, 0.f);
        float h3 = fmaxf(fmaf(coef, a.w, b.w) + bb.w, 0.f);
        __half2 hA = __float22half2_rn(make_float2(h0, h1));
        __half2 hB = __float22half2_rn(make_float2(h2, h3));
        float2 fA = __half22float2(hA);
        float2 fB = __half22float2(hB);
        __half2 lA = __float22half2_rn(make_float2(h0 - fA.x, h1 - fA.y));
        __half2 lB = __float22half2_rn(make_float2(h2 - fB.x, h3 - fB.y));
        *(uint2*)(dh + k * 2) = make_uint2(*(uint32_t*)&hA, *(uint32_t*)&hB);
        *(uint2*)(dl + k * 2) = make_uint2(*(uint32_t*)&lA, *(uint32_t*)&lB);
    };

    // guarded edge-index load for a tile (this warp's fixed row m_tile)
    auto load_idx = [&](int tile, int &r, int &c) {
        int e = tile * 128 + m_tile;
        int rr = 0, cc = 0;
        if (tile < T && e < E) { rr = ei[e]; cc = ei[E + e]; }
        if (rr < 0) rr = 0; if (rr >= N) rr = N - 1;
        if (cc < 0) cc = 0; if (cc >= N) cc = N - 1;
        r = rr; c = cc;
    };

    // synchronous gather (prologue only)
    auto gather_sync = [&](int tile, int buf) {
        int r, c;
        load_idx(tile, r, c);
        const float* yr = g_y + (long)r * YPITCH;
        const float* yc = g_y + (long)c * YPITCH;
        char* dh = Hrg_base + buf * HBUF;
        char* dl = dh + 4352;
#pragma unroll
        for (int i = 0; i < 8; i++) {
            int k = i * 16 + kpart;
            convert(*(const float4*)(yr + k), *(const float4*)(yc + k), k, dh, dl);
        }
    };

    // ldmatrix lane offsets (validated fragment math)
    uint32_t a_off = (uint32_t)(((lane & 7) + 8 * ((lane >> 3) & 1)) * PITCH + ((lane >> 4) & 1) * 16);
    uint32_t b_off = (uint32_t)((8 * ((lane >> 4) & 1) + (lane & 7)) * PITCH + ((lane >> 3) & 1) * 16);
    uint32_t w2_b = sb + OFF_W2 + (uint32_t)(ch * 64) * PITCH + b_off;
    uint32_t aA_base = sb + OFF_H + (uint32_t)rg * 8704u + a_off;

    int cq = (lane & 3) * 2;

    int rn = 0, cn = 0;   // indices for tile j+1
    if (nt_mine > 0) {
        gather_sync(bid, 0);
        load_idx(bid + G, rn, cn);
        BAR_PAIR(barid);
    }

    for (int j = 0; j < nt_mine; j++) {
        int cur = j & 1;
        int tile = bid + j * G;
        bool gon = (j + 1 < nt_mine);

        // capture gather sources for tile j+1, then prefetch indices for j+2
        const float* yr = g_y + (long)rn * YPITCH;
        const float* yc = g_y + (long)cn * YPITCH;
        load_idx(tile + 2 * G, rn, cn);

        char* dh = Hrg_base + (1 - cur) * HBUF;
        char* dl = dh + 4352;

        float acc[8][4];
#pragma unroll
        for (int t = 0; t < 8; t++) {
            float2 bv = *(const float2*)(b2s + ch * 64 + t * 8 + cq);
            acc[t][0] = bv.x; acc[t][1] = bv.y;
            acc[t][2] = bv.x; acc[t][3] = bv.y;
        }
        uint32_t ah_b = aA_base + (uint32_t)cur * (uint32_t)HBUF;
        uint32_t al_b = ah_b + 4352u;

        float4 ya[2], yb[2];   // in-flight gather chunks (depth 2)

#pragma unroll
        for (int s = 0; s < 8; s++) {
            // convert chunk s-2 (LDG issued 2 MMA-steps ago -> latency hidden)
            if (s >= 2 && gon) {
                int kc = (s - 2) * 16 + kpart;
                convert(ya[s & 1], yb[s & 1], kc, dh, dl);
            }
            // issue LDG chunk s into the slot just freed
            if (gon) {
                int k = s * 16 + kpart;
                ya[s & 1] = *(const float4*)(yr + k);
                yb[s & 1] = *(const float4*)(yc + k);
            }
            // MMA step ks = s on buf[cur]
            uint32_t koff = (uint32_t)s * 32u;
            uint32_t ah[4], al[4];
            LDSM_X4(ah[0], ah[1], ah[2], ah[3], ah_b + koff);
            LDSM_X4(al[0], al[1], al[2], al[3], al_b + koff);
#pragma unroll
            for (int pp = 0; pp < 2; pp++) {
                uint32_t p0 = (uint32_t)(pp * 2) * (16u * PITCH) + koff;
                uint32_t p1 = p0 + 16u * PITCH;
                uint32_t bh0, bh1, bh2, bh3, bh4, bh5, bh6, bh7;
                LDSM_X4(bh0, bh1, bh2, bh3, w2_b + p0);
                LDSM_X4(bh4, bh5, bh6, bh7, w2_b + p1);
                float* a0 = acc[pp * 4 + 0];
                float* a1 = acc[pp * 4 + 1];
                float* a2 = acc[pp * 4 + 2];
                float* a3 = acc[pp * 4 + 3];
                mma16816(a0, ah, bh0, bh1);
                mma16816(a1, ah, bh2, bh3);
                mma16816(a2, ah, bh4, bh5);
                mma16816(a3, ah, bh6, bh7);
                mma16816(a0, al, bh0, bh1);
                mma16816(a1, al, bh2, bh3);
                mma16816(a2, al, bh4, bh5);
                mma16816(a3, al, bh6, bh7);
            }
        }

        // tail converts: chunks 6 (slot 0) and 7 (slot 1)
        if (gon) {
            convert(ya[0], yb[0], 6 * 16 + kpart, dh, dl);
            convert(ya[1], yb[1], 7 * 16 + kpart, dh, dl);
        }

        // epilogue: scalar stores (121-float rows break 8B alignment on odd rows)
        int e0row = tile * 128 + rg * 16 + (lane >> 2);
        int e1row = e0row + 8;
        bool v0 = e0row < E, v1 = e1row < E;
        float* o0 = out + (long)e0row * OUT_CH;
        float* o1 = out + (long)e1row * OUT_CH;
#pragma unroll
        for (int t = 0; t < 8; t++) {
            int n0 = ch * 64 + t * 8 + cq;
            if (n0 < OUT_CH) {
                if (v0) o0[n0] = acc[t][0];
                if (v1) o1[n0] = acc[t][2];
                if (n0 + 1 < OUT_CH) {
                    if (v0) o0[n0 + 1] = acc[t][1];
                    if (v1) o1[n0 + 1] = acc[t][3];
                }
            }
        }

        // single pair barrier per tile: orders this tile's H writes (both warps)
        // before next iteration's MMA reads, and this tile's MMA reads before
        // the buffer is overwritten two iterations from now.
        BAR_PAIR(barid);
    }
}

extern "C" void kernel_launch(void* const* d_in, const int* in_sizes, int n_in,
                              void* d_out, int out_size) {
    const float* x   = (const float*)d_in[0];
    const int*   ei  = (const int*)d_in[1];
    const float* W1  = (const float*)d_in[2];
    const float* b1  = (const float*)d_in[3];
    const float* W2  = (const float*)d_in[4];
    const float* b2  = (const float*)d_in[5];
    const float* eps = (const float*)d_in[6];
    float* out = (float*)d_out;

    int N = in_sizes[0] / IN_CH;
    int E = in_sizes[1] / 2;
    int T = (E + 127) / 128;

    size_t smA = (size_t)(IN_CH * 132 + IN_CH * 128) * sizeof(float);
    cudaFuncSetAttribute(node_gemm, cudaFuncAttributeMaxDynamicSharedMemorySize, (int)smA);
    cudaFuncSetAttribute(edge_mma, cudaFuncAttributeMaxDynamicSharedMemorySize, SMEM_EDGE);

    node_gemm<<<(N + 127) / 128, 256, smA>>>(x, W1, N);

    int grid = 148; if (grid > T) grid = T;
    edge_mma<<<grid, 512, SMEM_EDGE>>>(ei, b1, W2, b2, eps, out, E, N, T);
}